// round 17
// baseline (speedup 1.0000x reference)
#include <cuda_runtime.h>
#include <cuda_fp16.h>
#include <cstdint>

#define BATCH   4
#define SEQ     8192
#define DIM     512
#define HEADS   8
#define NTOK    32768
#define QKVW    1536
#define SCALE_Q 0.125f
#define MTILES  256
#define PADT    133

// ---------------- scratch ----------------
__device__ __align__(16) __half g_a[(size_t)NTOK * DIM];
__device__ __align__(16) __half g_wq[(size_t)DIM * QKVW];
__device__ __align__(16) __half g_k[(size_t)NTOK * 512];   // head-major [b][h][n][64]
__device__ __align__(16) __half g_v[(size_t)NTOK * 512];   // head-major [b][h][n][64]
__device__ __align__(16) __half g_qh[(size_t)NTOK * 512];  // exp(q*scale) fp16
__device__ __align__(16) __half g_w2[(size_t)BATCH * DIM * DIM]; // per-batch fused ctx@w_out
__device__ float g_ctx[BATCH * HEADS * 64 * 64];
__device__ float g_qsum[BATCH * DIM];

// ---------------- PTX helpers (family-target-safe only) ----------------
__device__ __forceinline__ uint32_t s2u(const void* p) {
    uint32_t a;
    asm("{ .reg .u64 t; cvta.to.shared.u64 t, %1; cvt.u32.u64 %0, t; }" : "=r"(a) : "l"(p));
    return a;
}
#define CP16(d, s)                                                            \
    asm volatile("cp.async.cg.shared.global [%0], [%1], 16;" :: "r"(d), "l"(s) : "memory")
#define CPCOMMIT() asm volatile("cp.async.commit_group;" ::: "memory")
#define CPWAIT2()  asm volatile("cp.async.wait_group 2;" ::: "memory")
#define LDSM_X4(r, a)                                                         \
    asm volatile("ldmatrix.sync.aligned.m8n8.x4.shared.b16 {%0,%1,%2,%3}, [%4];" \
        : "=r"((r)[0]), "=r"((r)[1]), "=r"((r)[2]), "=r"((r)[3]) : "r"(a))
#define LDSM_X4T(r, a)                                                        \
    asm volatile("ldmatrix.sync.aligned.m8n8.x4.trans.shared.b16 {%0,%1,%2,%3}, [%4];" \
        : "=r"((r)[0]), "=r"((r)[1]), "=r"((r)[2]), "=r"((r)[3]) : "r"(a))
#define MMA(d, a, b)                                                          \
    asm volatile("mma.sync.aligned.m16n8k16.row.col.f32.f16.f16.f32 "         \
        "{%0,%1,%2,%3},{%4,%5,%6,%7},{%8,%9},{%0,%1,%2,%3};"                  \
        : "+f"((d)[0]), "+f"((d)[1]), "+f"((d)[2]), "+f"((d)[3])              \
        : "r"((a)[0]), "r"((a)[1]), "r"((a)[2]), "r"((a)[3]),                 \
          "r"((b)[0]), "r"((b)[1]))

// ---------------- weight fp32 -> fp16 + zero accumulators -------------------
__global__ __launch_bounds__(256) void wconv_kernel(const float* __restrict__ wq)
{
    int gid = blockIdx.x * 256 + threadIdx.x;
    int stride = gridDim.x * 256;
    for (int i = gid; i < DIM * QKVW; i += stride)
        g_wq[i] = __float2half_rn(wq[i]);
    if (gid < BATCH * HEADS * 64 * 64) g_ctx[gid] = 0.f;
    if (gid < BATCH * DIM) g_qsum[gid] = 0.f;
}

// ---------------- LayerNorm + transpose -> row-major fp16 (fp16 staging) ----
__global__ __launch_bounds__(256) void ln_kernel(
    const float* __restrict__ x, const float* __restrict__ lw,
    const float* __restrict__ lb)
{
    extern __shared__ __half s[];               // [512][33] halfs = 33792 B
    __shared__ float s_mu[32], s_rs[32];
    int tid = threadIdx.x;
    int token0 = blockIdx.x * 32;
    int b = token0 >> 13;
    int n0 = token0 & (SEQ - 1);
    const float* xb = x + (size_t)b * DIM * SEQ;

    #pragma unroll 4
    for (int i = 0; i < 64; i++) {
        int idx = i * 256 + tid;
        int d = idx >> 5, j = idx & 31;
        s[d * 33 + j] = __float2half_rn(xb[(size_t)d * SEQ + n0 + j]);
    }
    __syncthreads();

    int w = tid >> 5, lane = tid & 31;
    for (int t = 0; t < 4; t++) {
        int j = w * 4 + t;
        float sum = 0.f, sq = 0.f;
        #pragma unroll
        for (int d = lane; d < DIM; d += 32) {
            float v = __half2float(s[d * 33 + j]);
            sum += v; sq += v * v;
        }
        #pragma unroll
        for (int o = 16; o; o >>= 1) {
            sum += __shfl_xor_sync(0xffffffffu, sum, o);
            sq  += __shfl_xor_sync(0xffffffffu, sq, o);
        }
        if (lane == 0) {
            float mu = sum * (1.f / DIM);
            float var = sq * (1.f / DIM) - mu * mu;
            s_mu[j] = mu;
            s_rs[j] = rsqrtf(var + 1e-5f);
        }
    }
    __syncthreads();

    #pragma unroll
    for (int it = 0; it < 8; it++) {
        int idx = it * 256 + tid;
        int g = idx & 63, j = idx >> 6;
        int d0 = g * 8;
        float mu = s_mu[j], rs = s_rs[j];
        union { __half h[8]; uint4 u; } ph;
        #pragma unroll
        for (int i = 0; i < 8; i++) {
            int d = d0 + i;
            float v = (__half2float(s[d * 33 + j]) - mu) * rs * lw[d] + lb[d];
            ph.h[i] = __float2half_rn(v);
        }
        *(uint4*)&g_a[(size_t)(token0 + j) * DIM + d0] = ph.u;
    }
}

// ---------------- fp16 HMMA GEMM: C = A @ B, K=512 --------------------------
// 512 threads, 16 warps in 4x4 grid, 32x32 warp tiles. 4-stage cp.async
// pipeline (BK=32 per stage, wait_group 2 => prefetch distance 3).
// mode 0: qkv. q cols -> g_qh fp16 exp + colsums; k/v -> g_k/g_v fp16 head-major.
// mode 1: out[b][dout][n] = qh @ W2_b + bias (B indexed per batch).
#define SLICE 10496              // A 6144 + B 4352
#define STAGE (2 * SLICE)        // 20992
__global__ __launch_bounds__(512, 2) void mma_gemm_kernel(
    const __half* __restrict__ A, const __half* __restrict__ B,
    float* __restrict__ C, const float* __restrict__ bias, int ldb, int mode)
{
    extern __shared__ char smem[];
    uint32_t sb = s2u(smem);
    int tid = threadIdx.x, lane = tid & 31, wid = tid >> 5;
    int m0 = blockIdx.y * 128, n0 = blockIdx.x * 128;
    int wm = (wid >> 2) * 32, wn = (wid & 3) * 32;
    bool loader = (tid < 256);

    if (mode == 1) B += (size_t)(m0 >> 13) * DIM * DIM;   // per-batch W2

    int lt = tid & 255;
    int ar = lt >> 1, ah8 = (lt & 1) * 8;
    int bkr = lt >> 4, bn8 = (lt & 15) * 8;
    const __half* Ag = A + (size_t)(m0 + ar) * DIM + ah8;
    const __half* Bg = B + (size_t)bkr * ldb + n0 + bn8;
    uint32_t dA = sb + ar * 48 + ah8 * 2;
    uint32_t dB = sb + 6144 + bkr * 272 + bn8 * 2;

    uint32_t aAddr[2], bAddr[2];
    #pragma unroll
    for (int mi = 0; mi < 2; mi++)
        aAddr[mi] = sb + (wm + mi * 16 + (lane & 15)) * 48 + (lane >> 4) * 16;
    #pragma unroll
    for (int pi = 0; pi < 2; pi++)
        bAddr[pi] = sb + 6144 + (lane & 15) * 272 +
                    (wn + pi * 16 + (lane >> 4) * 8) * 2;

    float d[2][4][4];
    #pragma unroll
    for (int mi = 0; mi < 2; mi++)
        #pragma unroll
        for (int ni = 0; ni < 4; ni++)
            #pragma unroll
            for (int r = 0; r < 4; r++) d[mi][ni][r] = 0.f;

    if (loader) {
        #pragma unroll
        for (int p = 0; p < 3; p++) {
            #pragma unroll
            for (int s = 0; s < 2; s++) {
                uint32_t so = p * STAGE + s * SLICE;
                int ks = p * 2 + s;
                CP16(dA + so, Ag + ks * 16);
                CP16(dB + so, Bg + (size_t)ks * 16 * ldb);
            }
            CPCOMMIT();
        }
    }

    for (int kk = 0; kk < 16; kk++) {
        if (loader) CPWAIT2();
        __syncthreads();
        if (loader) {
            if (kk + 3 < 16) {
                #pragma unroll
                for (int s = 0; s < 2; s++) {
                    uint32_t so = ((kk + 3) & 3) * STAGE + s * SLICE;
                    int ks = (kk + 3) * 2 + s;
                    CP16(dA + so, Ag + ks * 16);
                    CP16(dB + so, Bg + (size_t)ks * 16 * ldb);
                }
            }
            CPCOMMIT();
        }

        #pragma unroll
        for (int s = 0; s < 2; s++) {
            uint32_t so = (kk & 3) * STAGE + s * SLICE;
            uint32_t ah[2][4], bh[2][4];
            #pragma unroll
            for (int mi = 0; mi < 2; mi++)
                LDSM_X4(ah[mi], aAddr[mi] + so);
            #pragma unroll
            for (int pi = 0; pi < 2; pi++)
                LDSM_X4T(bh[pi], bAddr[pi] + so);
            #pragma unroll
            for (int mi = 0; mi < 2; mi++)
                #pragma unroll
                for (int ni = 0; ni < 4; ni++)
                    MMA(d[mi][ni], ah[mi], &bh[ni >> 1][(ni & 1) * 2]);
        }
    }

    if (mode == 0) {
        int region = n0 >> 9;                  // 0: q, 1: k, 2: v
        if (region == 0) {
            float* qs = (float*)smem;
            __syncthreads();
            if (tid < 128) qs[tid] = 0.f;
            __syncthreads();
            #pragma unroll
            for (int mi = 0; mi < 2; mi++) {
                int r0 = m0 + wm + mi * 16 + (lane >> 2);
                #pragma unroll
                for (int ni = 0; ni < 4; ni++) {
                    int cl = wn + ni * 8 + (lane & 3) * 2;
                    float v0 = __expf(d[mi][ni][0] * SCALE_Q);
                    float v1 = __expf(d[mi][ni][1] * SCALE_Q);
                    float v2 = __expf(d[mi][ni][2] * SCALE_Q);
                    float v3 = __expf(d[mi][ni][3] * SCALE_Q);
                    atomicAdd(&qs[cl],     v0 + v2);
                    atomicAdd(&qs[cl + 1], v1 + v3);
                    *(__half2*)&g_qh[(size_t)r0 * 512 + n0 + cl] =
                        __floats2half2_rn(v0, v1);
                    *(__half2*)&g_qh[(size_t)(r0 + 8) * 512 + n0 + cl] =
                        __floats2half2_rn(v2, v3);
                }
            }
            __syncthreads();
            if (tid < 128)
                atomicAdd(&g_qsum[(m0 >> 13) * DIM + n0 + tid], qs[tid]);
        } else {
            __half* dstbuf = (region == 1) ? g_k : g_v;
            int colbase = n0 & 511;
            #pragma unroll
            for (int mi = 0; mi < 2; mi++) {
                int r0 = m0 + wm + mi * 16 + (lane >> 2);
                int b = r0 >> 13, n = r0 & (SEQ - 1);
                #pragma unroll
                for (int ni = 0; ni < 4; ni++) {
                    int col = colbase + wn + ni * 8 + (lane & 3) * 2;
                    int h = col >> 6, dd = col & 63;
                    size_t base = ((size_t)(b * HEADS + h) * SEQ + n) * 64 + dd;
                    *(__half2*)&dstbuf[base] =
                        __floats2half2_rn(d[mi][ni][0], d[mi][ni][1]);
                    *(__half2*)&dstbuf[base + 8 * 64] =
                        __floats2half2_rn(d[mi][ni][2], d[mi][ni][3]);
                }
            }
        }
    } else {
        __syncthreads();
        float* st = (float*)smem;             // [128][PADT]
        #pragma unroll
        for (int mi = 0; mi < 2; mi++) {
            int r0 = wm + mi * 16 + (lane >> 2);
            #pragma unroll
            for (int ni = 0; ni < 4; ni++) {
                int c0 = wn + ni * 8 + (lane & 3) * 2;
                st[r0 * PADT + c0]           = d[mi][ni][0];
                st[r0 * PADT + c0 + 1]       = d[mi][ni][1];
                st[(r0 + 8) * PADT + c0]     = d[mi][ni][2];
                st[(r0 + 8) * PADT + c0 + 1] = d[mi][ni][3];
            }
        }
        __syncthreads();
        int b = m0 >> 13, nn0 = m0 & (SEQ - 1);
        float* dst = C + (size_t)b * DIM * SEQ + (size_t)n0 * SEQ + nn0;
        for (int idx = tid; idx < 16384; idx += 512) {
            int r = idx >> 7;
            int c = idx & 127;
            dst[(size_t)r * SEQ + c] = st[c * PADT + r] + bias[n0 + r];
        }
    }
}

// ---------------- ctx = softmax_d(k)^T @ v per (b,h) on tensor cores --------
// grid (SEQ/512, 32 bh) = 512 blocks (fills the chip), 256 threads.
#define TOKCH 512
#define SUBT  128
#define KTP   72                 // padded row stride in halfs (144B)
__global__ __launch_bounds__(256, 3) void ctx_mma_kernel()
{
    __shared__ __half kt[SUBT * KTP];
    __shared__ __half vt[SUBT * KTP];
    int tid = threadIdx.x, lane = tid & 31, wid = tid >> 5;
    int bh = blockIdx.y;
    int tok0 = blockIdx.x * TOKCH;
    const __half* kbase = g_k + (size_t)bh * SEQ * 64;
    const __half* vbase = g_v + (size_t)bh * SEQ * 64;

    int wm = (wid & 3) * 16, wn = (wid >> 2) * 32;
    int l7 = lane & 7, sel = lane >> 3;
    uint32_t aBase = s2u(kt) + (uint32_t)((((sel >> 1) * 8) + l7) * KTP + wm + (sel & 1) * 8) * 2;
    uint32_t bBase[2];
    #pragma unroll
    for (int pi = 0; pi < 2; pi++)
        bBase[pi] = s2u(vt) + (uint32_t)((lane & 15) * KTP + wn + pi * 16 +
                                         (lane >> 4) * 8) * 2;

    float acc[4][4] = {};
    int t = tid >> 1, h4 = tid & 1;

    for (int st0 = 0; st0 < TOKCH; st0 += SUBT) {
        const uint4* kr4 = (const uint4*)(kbase + (size_t)(tok0 + st0 + t) * 64 + h4 * 32);
        uint4 kr[4];
        #pragma unroll
        for (int i = 0; i < 4; i++) kr[i] = kr4[i];
        float e[32];
        float s = 0.f;
        #pragma unroll
        for (int i = 0; i < 4; i++) {
            const __half2* hp = (const __half2*)&kr[i];
            #pragma unroll
            for (int j = 0; j < 4; j++) {
                float2 f = __half22float2(hp[j]);
                float e0 = __expf(f.x), e1 = __expf(f.y);
                e[i * 8 + j * 2] = e0;
                e[i * 8 + j * 2 + 1] = e1;
                s += e0 + e1;
            }
        }
        s += __shfl_xor_sync(0xffffffffu, s, 1);
        float inv = 1.f / s;
        #pragma unroll
        for (int i = 0; i < 4; i++) {
            uint4 kw;
            __half2* op = (__half2*)&kw;
            #pragma unroll
            for (int j = 0; j < 4; j++)
                op[j] = __floats2half2_rn(e[i * 8 + j * 2] * inv,
                                          e[i * 8 + j * 2 + 1] * inv);
            *(uint4*)&kt[t * KTP + h4 * 32 + i * 8] = kw;
        }
        const uint4* vr4 = (const uint4*)(vbase + (size_t)(tok0 + st0 + t) * 64 + h4 * 32);
        #pragma unroll
        for (int i = 0; i < 4; i++)
            *(uint4*)&vt[t * KTP + h4 * 32 + i * 8] = vr4[i];
        __syncthreads();

        #pragma unroll
        for (int k16 = 0; k16 < SUBT; k16 += 16) {
            uint32_t a[4];
            LDSM_X4T(a, aBase + (uint32_t)k16 * (KTP * 2));
            #pragma unroll
            for (int pi = 0; pi < 2; pi++) {
                uint32_t bb[4];
                LDSM_X4T(bb, bBase[pi] + (uint32_t)k16 * (KTP * 2));
                MMA(acc[pi * 2],     a, &bb[0]);
                MMA(acc[pi * 2 + 1], a, &bb[2]);
            }
        }
        __syncthreads();
    }

    float* cb = g_ctx + (size_t)bh * 4096;
    int r = wm + (lane >> 2);
    #pragma unroll
    for (int ni = 0; ni < 4; ni++) {
        int c = wn + ni * 8 + (lane & 3) * 2;
        atomicAdd(&cb[r * 64 + c],           acc[ni][0]);
        atomicAdd(&cb[r * 64 + c + 1],       acc[ni][1]);
        atomicAdd(&cb[(r + 8) * 64 + c],     acc[ni][2]);
        atomicAdd(&cb[(r + 8) * 64 + c + 1], acc[ni][3]);
    }
}

// ---------------- W2_b = vstack_h( diag(rq_h) * (ctx_bh @ w_out_h) ) --------
__global__ __launch_bounds__(256) void w2_kernel(const float* __restrict__ w_out)
{
    __shared__ float cs[64][65];
    __shared__ float ws[64][128];
    int tid = threadIdx.x;
    int jc = blockIdx.x;
    int bh = blockIdx.y;
    int b = bh >> 3, h = bh & 7;

    const float* csrc = g_ctx + (size_t)bh * 4096;
    for (int i = tid; i < 4096; i += 256) cs[i >> 6][i & 63] = csrc[i];
    for (int i = tid; i < 64 * 128; i += 256) {
        int e = i >> 7, j = i & 127;
        ws[e][j] = w_out[(size_t)(h * 64 + e) * DIM + jc * 128 + j];
    }
    __syncthreads();

    int dd = tid >> 2, j0 = (tid & 3) * 32;
    float rq = 1.f / g_qsum[b * DIM + h * 64 + dd];
    float acc[32] = {};
    #pragma unroll 8
    for (int e = 0; e < 64; e++) {
        float a = cs[dd][e];
        #pragma unroll
        for (int j = 0; j < 32; j++) acc[j] += a * ws[e][j0 + j];
    }
    __half* dst = g_w2 + ((size_t)b * DIM + h * 64 + dd) * DIM + jc * 128 + j0;
    #pragma unroll
    for (int j = 0; j < 32; j += 2)
        *(__half2*)&dst[j] = __floats2half2_rn(acc[j] * rq, acc[j + 1] * rq);
}

// ---------------- launch ------------------------------------------------------
extern "C" void kernel_launch(void* const* d_in, const int* in_sizes, int n_in,
                              void* d_out, int out_size)
{
    const float* x     = (const float*)d_in[0];
    const float* ln_w  = (const float*)d_in[1];
    const float* ln_b  = (const float*)d_in[2];
    const float* w_qkv = (const float*)d_in[3];
    const float* w_out = (const float*)d_in[4];
    const float* b_out = (const float*)d_in[5];
    float* out = (float*)d_out;

    __half *p_a, *p_wq, *p_qh, *p_w2;
    cudaGetSymbolAddress((void**)&p_a, g_a);
    cudaGetSymbolAddress((void**)&p_wq, g_wq);
    cudaGetSymbolAddress((void**)&p_qh, g_qh);
    cudaGetSymbolAddress((void**)&p_w2, g_w2);

    const int LN_SMEM   = 512 * 33 * 2;      // 33792 (fp16 staging)
    const int GEMM_SMEM = 4 * STAGE;         // 83968 >= epilogue 68096
    cudaFuncSetAttribute(ln_kernel, cudaFuncAttributeMaxDynamicSharedMemorySize, LN_SMEM);
    cudaFuncSetAttribute(mma_gemm_kernel, cudaFuncAttributeMaxDynamicSharedMemorySize, GEMM_SMEM);

    wconv_kernel<<<768, 256>>>(w_qkv);
    ln_kernel<<<NTOK / 32, 256, LN_SMEM>>>(x, ln_w, ln_b);
    mma_gemm_kernel<<<dim3(QKVW / 128, MTILES), 512, GEMM_SMEM>>>(
        p_a, p_wq, nullptr, nullptr, QKVW, 0);
    ctx_mma_kernel<<<dim3(SEQ / TOKCH, BATCH * HEADS), 256>>>();
    w2_kernel<<<dim3(4, 32), 256>>>(w_out);
    mma_gemm_kernel<<<dim3(DIM / 128, MTILES), 512, GEMM_SMEM>>>(
        p_qh, p_w2, out, b_out, DIM, 1);
}